// round 14
// baseline (speedup 1.0000x reference)
#include <cuda_runtime.h>
#include <cuda_fp16.h>
#include <cstdint>

#define Bn 32
#define Hn 384
#define Wn 384
#define NPIX (Bn*Hn*Wn)          // 4,718,592
#define NELEM (NPIX*8)           // 37,748,736

#define TILE_X 128
#define ROWS_PER 16              // rows per tile
#define RPASS 4                  // output rows per pass
#define RPITCH 136               // smem row pitch in pixels
#define RING 14                  // ring slots = live set (10 + 4 prefetch)

#define GRID_CTAS 740            // 148 SMs x 5 CTAs: one full wave
#define NTILES (3*24*32)         // 2304

// Scratch (__device__ globals: allocation-free rule)
__device__ __half g_qA[NELEM];
__device__ __half g_qB[NELEM];
__device__ float  g_u[NELEM];    // holds uW = W^T u - b (per pixel)
__device__ int    g_ctr[8];      // one tile counter per k_iter launch

// ---------- helpers ----------
__device__ __forceinline__ uint32_t smem_u32(const void* p) {
    uint32_t a;
    asm("{ .reg .u64 t; cvta.to.shared.u64 t, %1; cvt.u32.u64 %0, t; }"
        : "=r"(a) : "l"(p));
    return a;
}
__device__ __forceinline__ void ldm4(uint32_t& a0, uint32_t& a1,
                                     uint32_t& a2, uint32_t& a3, uint32_t addr) {
    asm volatile("ldmatrix.sync.aligned.m8n8.x4.shared.b16 {%0,%1,%2,%3},[%4];"
                 : "=r"(a0), "=r"(a1), "=r"(a2), "=r"(a3) : "r"(addr));
}
__device__ __forceinline__ void hmma(float* d, uint32_t a0, uint32_t a1,
                                     uint32_t a2, uint32_t a3,
                                     uint32_t b0, uint32_t b1) {
    asm volatile("mma.sync.aligned.m16n8k16.row.col.f32.f16.f16.f32 "
                 "{%0,%1,%2,%3},{%4,%5,%6,%7},{%8,%9},{%0,%1,%2,%3};"
                 : "+f"(d[0]), "+f"(d[1]), "+f"(d[2]), "+f"(d[3])
                 : "r"(a0), "r"(a1), "r"(a2), "r"(a3), "r"(b0), "r"(b1));
}
__device__ __forceinline__ void cpa16(uint32_t dst, const void* src, int sz) {
    asm volatile("cp.async.cg.shared.global [%0], [%1], 16, %2;"
                 :: "r"(dst), "l"(src), "r"(sz) : "memory");
}
__device__ __forceinline__ void cpa_commit() {
    asm volatile("cp.async.commit_group;" ::: "memory");
}
__device__ __forceinline__ void cpa_wait0() {
    asm volatile("cp.async.wait_group 0;" ::: "memory");
}
__device__ __forceinline__ uint32_t h2pack(float a, float b) {
    __half2 h = __floats2half2_rn(a, b);
    return *reinterpret_cast<uint32_t*>(&h);
}

// ============================================================
// init: q0 = softmax(x) (fp16);
//       uW = W^T * (-log(max(q0,1e-6))) - b   (fp32, per pixel)
// Also resets the per-launch tile counters.
// ============================================================
__global__ void k_init(const float* __restrict__ x,
                       const float* __restrict__ wsc,   // [8,8] W[c][d]
                       const float* __restrict__ bsc,   // [8]
                       __half* __restrict__ q,
                       float* __restrict__ uw) {
    __shared__ float sW[64];
    __shared__ float sB[8];
    int gti = blockIdx.x * blockDim.x + threadIdx.x;
    if (threadIdx.x < 64) sW[threadIdx.x] = wsc[threadIdx.x];
    if (threadIdx.x < 8)  sB[threadIdx.x] = bsc[threadIdx.x];
    if (gti < 8) g_ctr[gti] = GRID_CTAS;
    __syncthreads();
    int i = gti;
    if (i >= NPIX) return;
    const float4* xp = reinterpret_cast<const float4*>(x) + (long)i * 2;
    float4 a = xp[0], b4 = xp[1];
    float v[8] = {a.x, a.y, a.z, a.w, b4.x, b4.y, b4.z, b4.w};
    float m = v[0];
#pragma unroll
    for (int c = 1; c < 8; c++) m = fmaxf(m, v[c]);
    float e[8], s = 0.f;
#pragma unroll
    for (int c = 0; c < 8; c++) { e[c] = __expf(v[c] - m); s += e[c]; }
    float inv = 1.f / s;
    float qq[8], uu[8];
#pragma unroll
    for (int c = 0; c < 8; c++) {
        qq[c] = e[c] * inv;
        uu[c] = -__logf(fmaxf(qq[c], 1e-6f));
    }

    uint4 qv;
    qv.x = h2pack(qq[0], qq[1]);
    qv.y = h2pack(qq[2], qq[3]);
    qv.z = h2pack(qq[4], qq[5]);
    qv.w = h2pack(qq[6], qq[7]);
    reinterpret_cast<uint4*>(q)[i] = qv;

    float uwv[8];
#pragma unroll
    for (int d = 0; d < 8; d++) {
        float acc = -sB[d];
#pragma unroll
        for (int c = 0; c < 8; c++) acc = fmaf(uu[c], sW[c * 8 + d], acc);
        uwv[d] = acc;
    }
    float4* up = reinterpret_cast<float4*>(uw) + (long)i * 2;
    up[0] = make_float4(uwv[0], uwv[1], uwv[2], uwv[3]);
    up[1] = make_float4(uwv[4], uwv[5], uwv[6], uwv[7]);
}

// ============================================================
// One mean-field iteration. Persistent CTAs pull tiles from an
// atomic queue. Conv weights are pre-multiplied by W (k' = k.W),
// so out = -(uW + conv(q,k')) -- no 1x1 in the epilogue.
// ============================================================
__global__ __launch_bounds__(128, 5)
void k_iter(const __half* __restrict__ qin,
            const float* __restrict__ uw,
            const float* __restrict__ kw,      // [7,7,8,8] fp32
            const float* __restrict__ wsc,     // [8,8] (for k' fold)
            __half* __restrict__ qout,
            float* __restrict__ logits_out,    // non-null on last iter
            int ctr_idx) {
    __shared__ __align__(16) __half sq[RING][RPITCH][8];  // 30,464 B
    __shared__ __align__(16) uint2  sbfrag[7][4][32];     // 7,168 B
    __shared__ __align__(16) float  sst[4][32][10];       // 5,120 B
    __shared__ int   s_t;

    const int tid = threadIdx.x;
    const int w = tid >> 5;
    const int lane = tid & 31;

    // ---- B fragments (once per CTA): k'[dy][dx][ci][d] = sum_co kmask*W ----
    for (int idx = tid; idx < 7 * 4 * 32; idx += 128) {
        int l = idx & 31, dxp = (idx >> 5) & 3, dy = idx >> 7;
        int t = l & 3, g = l >> 2;
        int dx0 = dxp * 2, dx1 = dx0 + 1;
        int c0 = 2 * t, c1 = 2 * t + 1;
        float w00 = 0.f, w01 = 0.f, w10 = 0.f, w11 = 0.f;
#pragma unroll
        for (int co = 0; co < 8; co++) {
            float wg = __ldg(&wsc[co * 8 + g]);
            if (co != c0) w00 = fmaf(__ldg(&kw[((dy * 7 + dx0) * 8 + c0) * 8 + co]), wg, w00);
            if (co != c1) w01 = fmaf(__ldg(&kw[((dy * 7 + dx0) * 8 + c1) * 8 + co]), wg, w01);
            if (dx1 < 7) {
                if (co != c0) w10 = fmaf(__ldg(&kw[((dy * 7 + dx1) * 8 + c0) * 8 + co]), wg, w10);
                if (co != c1) w11 = fmaf(__ldg(&kw[((dy * 7 + dx1) * 8 + c1) * 8 + co]), wg, w11);
            }
        }
        sbfrag[dy][dxp][l] = make_uint2(h2pack(w00, w01), h2pack(w10, w11));
    }
    if (tid < 2 * RING) {  // zero slack pixels 134,135 of every ring slot
        uint4 z = make_uint4(0, 0, 0, 0);
        *reinterpret_cast<uint4*>(&sq[tid >> 1][134 + (tid & 1)][0]) = z;
    }

    const uint32_t ring0 = smem_u32(sq);
    const uint32_t lofs = (uint32_t)(((lane & 15) + (lane >> 4)) * 16);
    const uint32_t wbase = (uint32_t)(w * 32 * 16);

    int tile = blockIdx.x;          // first tile without touching the counter

    while (tile < NTILES) {
        const int bx = tile % 3;
        const int rest = tile / 3;
        const int by = rest % 24;
        const int bz = rest / 24;
        const int x0 = bx * TILE_X;
        const int y0 = by * ROWS_PER;
        const uint4* qb = reinterpret_cast<const uint4*>(qin) + (long)bz * Hn * Wn;

        auto slot_of = [&](int gy) { return (gy + 3) % RING; };
        auto async_row = [&](int gy) {
            uint32_t dst0 = smem_u32(&sq[slot_of(gy)][0][0]);
            const bool rowok = (unsigned)gy < (unsigned)Hn;
            const int gyc = rowok ? gy : 0;
            const uint4* rowp = qb + (long)gyc * Wn;
            for (int i = tid; i < 134; i += 128) {
                int gx = x0 - 3 + i;
                bool ok = rowok && (unsigned)gx < (unsigned)Wn;
                int gxc = ((unsigned)gx < (unsigned)Wn) ? gx : 0;
                cpa16(dst0 + (uint32_t)i * 16u, rowp + gxc, ok ? 16 : 0);
            }
        };

        for (int gy = y0 - 3; gy <= y0 + 6; ++gy) async_row(gy);
        cpa_commit();
        cpa_wait0();
        __syncthreads();

        for (int p = 0; p < ROWS_PER / RPASS; ++p) {
            const int y = y0 + p * RPASS;
            if (p < ROWS_PER / RPASS - 1) {
                for (int gy = y + 7; gy <= y + 10; ++gy) async_row(gy);
                cpa_commit();
            }

            float acc[RPASS][8];
#pragma unroll
            for (int r = 0; r < RPASS; ++r)
#pragma unroll
                for (int j = 0; j < 8; ++j) acc[r][j] = 0.f;

            const int slot0 = y % RING;

#pragma unroll
            for (int dxp = 0; dxp < 4; ++dxp) {
                uint2 bf[7];
#pragma unroll
                for (int dy = 0; dy < 7; ++dy) bf[dy] = sbfrag[dy][dxp][lane];

#pragma unroll
                for (int si = 0; si < 10; ++si) {
                    const int sy = si - 3;
                    int slot = slot0 + si;
                    if (slot >= RING) slot -= RING;
                    const uint32_t abase = ring0 + (uint32_t)(slot * (RPITCH * 16))
                                         + wbase + lofs + (uint32_t)(dxp * 32);
                    uint32_t a0, a1, a2, a3, c0, c1, c2, c3;
                    ldm4(a0, a1, a2, a3, abase);
                    ldm4(c0, c1, c2, c3, abase + 256);
                    const int rlo = (sy - 3 < 0) ? 0 : sy - 3;
                    const int rhi = (sy + 3 > RPASS - 1) ? RPASS - 1 : sy + 3;
#pragma unroll
                    for (int r = rlo; r <= rhi; ++r) {
                        const int dy = sy - r + 3;
                        hmma(acc[r], a0, a1, a2, a3, bf[dy].x, bf[dy].y);
                        hmma(acc[r] + 4, c0, c1, c2, c3, bf[dy].x, bf[dy].y);
                    }
                }
            }

            // ---- epilogue: out = -(uW + pen), then softmax / store ----
            const int g = lane >> 2, t = lane & 3;
#pragma unroll
            for (int r = 0; r < RPASS; ++r) {
                __syncwarp();
                *reinterpret_cast<float2*>(&sst[w][g][2 * t])      = make_float2(acc[r][0], acc[r][1]);
                *reinterpret_cast<float2*>(&sst[w][g + 8][2 * t])  = make_float2(acc[r][2], acc[r][3]);
                *reinterpret_cast<float2*>(&sst[w][g + 16][2 * t]) = make_float2(acc[r][4], acc[r][5]);
                *reinterpret_cast<float2*>(&sst[w][g + 24][2 * t]) = make_float2(acc[r][6], acc[r][7]);
                __syncwarp();
                float pen[8];
#pragma unroll
                for (int c = 0; c < 4; ++c) {
                    float2 v = *reinterpret_cast<float2*>(&sst[w][lane][2 * c]);
                    pen[2 * c] = v.x; pen[2 * c + 1] = v.y;
                }

                const long gi = ((long)(bz * Hn + y + r) * Wn + x0 + w * 32 + lane) * 8;
                float4 uA = *reinterpret_cast<const float4*>(uw + gi);
                float4 uB = *reinterpret_cast<const float4*>(uw + gi + 4);
                float out[8];
                out[0] = -(uA.x + pen[0]); out[1] = -(uA.y + pen[1]);
                out[2] = -(uA.z + pen[2]); out[3] = -(uA.w + pen[3]);
                out[4] = -(uB.x + pen[4]); out[5] = -(uB.y + pen[5]);
                out[6] = -(uB.z + pen[6]); out[7] = -(uB.w + pen[7]);

                if (logits_out) {
                    float4* lo = reinterpret_cast<float4*>(logits_out + gi);
                    lo[0] = make_float4(out[0], out[1], out[2], out[3]);
                    lo[1] = make_float4(out[4], out[5], out[6], out[7]);
                } else {
                    float m = out[0];
#pragma unroll
                    for (int c = 1; c < 8; c++) m = fmaxf(m, out[c]);
                    float e[8], s = 0.f;
#pragma unroll
                    for (int c = 0; c < 8; c++) { e[c] = __expf(out[c] - m); s += e[c]; }
                    float inv = 1.f / s;
                    uint4 qv;
                    qv.x = h2pack(e[0] * inv, e[1] * inv);
                    qv.y = h2pack(e[2] * inv, e[3] * inv);
                    qv.z = h2pack(e[4] * inv, e[5] * inv);
                    qv.w = h2pack(e[6] * inv, e[7] * inv);
                    reinterpret_cast<uint4*>(qout)[gi >> 3] = qv;
                }
            }

            if (p < ROWS_PER / RPASS - 1) cpa_wait0();
            __syncthreads();
        }

        // ---- grab next tile ----
        if (tid == 0) s_t = atomicAdd(&g_ctr[ctr_idx], 1);
        __syncthreads();
        tile = s_t;
        __syncthreads();
    }
}

// ============================================================
extern "C" void kernel_launch(void* const* d_in, const int* in_sizes, int n_in,
                              void* d_out, int out_size) {
    const float* x  = (const float*)d_in[0];
    const float* kw = (const float*)d_in[1];
    const float* ws = (const float*)d_in[2];
    const float* bs = (const float*)d_in[3];

    __half *qA, *qB;
    float* uu;
    cudaGetSymbolAddress((void**)&qA, g_qA);
    cudaGetSymbolAddress((void**)&qB, g_qB);
    cudaGetSymbolAddress((void**)&uu, g_u);

    k_init<<<(NPIX + 255) / 256, 256>>>(x, ws, bs, qA, uu);

    __half* src = qA;
    __half* dst = qB;
    for (int it = 0; it < 5; it++) {
        float* lo = (it == 4) ? (float*)d_out : nullptr;
        k_iter<<<GRID_CTAS, 128>>>(src, uu, kw, ws, dst, lo, it);
        __half* t = src; src = dst; dst = t;
    }
}

// round 16
// speedup vs baseline: 1.4592x; 1.4592x over previous
#include <cuda_runtime.h>
#include <cuda_fp16.h>
#include <cstdint>

#define Bn 32
#define Hn 384
#define Wn 384
#define NPIX (Bn*Hn*Wn)          // 4,718,592
#define NELEM (NPIX*8)           // 37,748,736

#define TILE_X 128
#define ROWS_PER 16              // rows per tile
#define RPASS 4                  // output rows per pass
#define RPITCH 136               // smem row pitch in pixels
#define RING 14                  // ring slots = live set (10 + 4 prefetch)

#define GRID_CTAS 740            // 148 SMs x 5 CTAs: one full wave
#define NTILES (3*24*32)         // 2304

// Scratch (__device__ globals: allocation-free rule)
__device__ __half g_qA[NELEM];
__device__ __half g_qB[NELEM];
__device__ float  g_u[NELEM];    // holds uW = W^T u - b (per pixel)
__device__ int    g_ctr[8];      // one tile counter per k_iter launch

// ---------- helpers ----------
__device__ __forceinline__ uint32_t smem_u32(const void* p) {
    uint32_t a;
    asm("{ .reg .u64 t; cvta.to.shared.u64 t, %1; cvt.u32.u64 %0, t; }"
        : "=r"(a) : "l"(p));
    return a;
}
__device__ __forceinline__ void ldm4(uint32_t& a0, uint32_t& a1,
                                     uint32_t& a2, uint32_t& a3, uint32_t addr) {
    asm volatile("ldmatrix.sync.aligned.m8n8.x4.shared.b16 {%0,%1,%2,%3},[%4];"
                 : "=r"(a0), "=r"(a1), "=r"(a2), "=r"(a3) : "r"(addr));
}
__device__ __forceinline__ void hmma(float* d, uint32_t a0, uint32_t a1,
                                     uint32_t a2, uint32_t a3,
                                     uint32_t b0, uint32_t b1) {
    asm volatile("mma.sync.aligned.m16n8k16.row.col.f32.f16.f16.f32 "
                 "{%0,%1,%2,%3},{%4,%5,%6,%7},{%8,%9},{%0,%1,%2,%3};"
                 : "+f"(d[0]), "+f"(d[1]), "+f"(d[2]), "+f"(d[3])
                 : "r"(a0), "r"(a1), "r"(a2), "r"(a3), "r"(b0), "r"(b1));
}
__device__ __forceinline__ void cpa16(uint32_t dst, const void* src, int sz) {
    asm volatile("cp.async.cg.shared.global [%0], [%1], 16, %2;"
                 :: "r"(dst), "l"(src), "r"(sz) : "memory");
}
__device__ __forceinline__ void cpa_commit() {
    asm volatile("cp.async.commit_group;" ::: "memory");
}
__device__ __forceinline__ void cpa_wait0() {
    asm volatile("cp.async.wait_group 0;" ::: "memory");
}
__device__ __forceinline__ uint32_t h2pack(float a, float b) {
    __half2 h = __floats2half2_rn(a, b);
    return *reinterpret_cast<uint32_t*>(&h);
}

// ============================================================
// init: q0 = softmax(x) (fp16);
//       uW = W^T * (-log(max(q0,1e-6))) - b   (fp32, per pixel)
// Also resets the per-launch tile counters.
// ============================================================
__global__ void k_init(const float* __restrict__ x,
                       const float* __restrict__ wsc,   // [8,8] W[c][d]
                       const float* __restrict__ bsc,   // [8]
                       __half* __restrict__ q,
                       float* __restrict__ uw) {
    __shared__ float sW[64];
    __shared__ float sB[8];
    int gti = blockIdx.x * blockDim.x + threadIdx.x;
    if (threadIdx.x < 64) sW[threadIdx.x] = wsc[threadIdx.x];
    if (threadIdx.x < 8)  sB[threadIdx.x] = bsc[threadIdx.x];
    if (gti < 8) g_ctr[gti] = GRID_CTAS;
    __syncthreads();
    int i = gti;
    if (i >= NPIX) return;
    const float4* xp = reinterpret_cast<const float4*>(x) + (long)i * 2;
    float4 a = xp[0], b4 = xp[1];
    float v[8] = {a.x, a.y, a.z, a.w, b4.x, b4.y, b4.z, b4.w};
    float m = v[0];
#pragma unroll
    for (int c = 1; c < 8; c++) m = fmaxf(m, v[c]);
    float e[8], s = 0.f;
#pragma unroll
    for (int c = 0; c < 8; c++) { e[c] = __expf(v[c] - m); s += e[c]; }
    float inv = 1.f / s;
    float qq[8], uu[8];
#pragma unroll
    for (int c = 0; c < 8; c++) {
        qq[c] = e[c] * inv;
        uu[c] = -__logf(fmaxf(qq[c], 1e-6f));
    }

    uint4 qv;
    qv.x = h2pack(qq[0], qq[1]);
    qv.y = h2pack(qq[2], qq[3]);
    qv.z = h2pack(qq[4], qq[5]);
    qv.w = h2pack(qq[6], qq[7]);
    reinterpret_cast<uint4*>(q)[i] = qv;

    float uwv[8];
#pragma unroll
    for (int d = 0; d < 8; d++) {
        float acc = -sB[d];
#pragma unroll
        for (int c = 0; c < 8; c++) acc = fmaf(uu[c], sW[c * 8 + d], acc);
        uwv[d] = acc;
    }
    float4* up = reinterpret_cast<float4*>(uw) + (long)i * 2;
    up[0] = make_float4(uwv[0], uwv[1], uwv[2], uwv[3]);
    up[1] = make_float4(uwv[4], uwv[5], uwv[6], uwv[7]);
}

// ============================================================
// One mean-field iteration. Persistent CTAs pull tiles from an
// atomic queue. Conv weights are pre-multiplied by W (k' = k.W),
// so out = -(uW + conv(q,k')) -- no 1x1 in the epilogue.
// ============================================================
__global__ __launch_bounds__(128, 5)
void k_iter(const __half* __restrict__ qin,
            const float* __restrict__ uw,
            const float* __restrict__ kw,      // [7,7,8,8] fp32
            const float* __restrict__ wsc,     // [8,8] (for k' fold)
            __half* __restrict__ qout,
            float* __restrict__ logits_out,    // non-null on last iter
            int ctr_idx) {
    __shared__ __align__(16) __half sq[RING][RPITCH][8];  // 30,464 B
    __shared__ __align__(16) uint2  sbfrag[7][4][32];     // 7,168 B
    __shared__ __align__(16) float  sst[4][32][10];       // 5,120 B
    __shared__ float sW[64];
    __shared__ int   s_t;

    const int tid = threadIdx.x;
    const int w = tid >> 5;
    const int lane = tid & 31;

    if (tid < 64) sW[tid] = wsc[tid];
    __syncthreads();

    // ---- B fragments (once per CTA): k'[dy][dx][ci][d] = sum_co kmask*W ----
    for (int idx = tid; idx < 7 * 4 * 32; idx += 128) {
        int l = idx & 31, dxp = (idx >> 5) & 3, dy = idx >> 7;
        int t = l & 3, g = l >> 2;
        int dx0 = dxp * 2, dx1 = dx0 + 1;
        int c0 = 2 * t, c1 = 2 * t + 1;
        float w00 = 0.f, w01 = 0.f, w10 = 0.f, w11 = 0.f;
#pragma unroll
        for (int co = 0; co < 8; co++) {
            float wg = sW[co * 8 + g];
            if (co != c0) w00 = fmaf(__ldg(&kw[((dy * 7 + dx0) * 8 + c0) * 8 + co]), wg, w00);
            if (co != c1) w01 = fmaf(__ldg(&kw[((dy * 7 + dx0) * 8 + c1) * 8 + co]), wg, w01);
            if (dx1 < 7) {
                if (co != c0) w10 = fmaf(__ldg(&kw[((dy * 7 + dx1) * 8 + c0) * 8 + co]), wg, w10);
                if (co != c1) w11 = fmaf(__ldg(&kw[((dy * 7 + dx1) * 8 + c1) * 8 + co]), wg, w11);
            }
        }
        sbfrag[dy][dxp][l] = make_uint2(h2pack(w00, w01), h2pack(w10, w11));
    }
    if (tid < 2 * RING) {  // zero slack pixels 134,135 of every ring slot
        uint4 z = make_uint4(0, 0, 0, 0);
        *reinterpret_cast<uint4*>(&sq[tid >> 1][134 + (tid & 1)][0]) = z;
    }

    const uint32_t ring0 = smem_u32(sq);
    const uint32_t lofs = (uint32_t)(((lane & 15) + (lane >> 4)) * 16);
    const uint32_t wbase = (uint32_t)(w * 32 * 16);

    int tile = blockIdx.x;          // first tile without touching the counter

    while (tile < NTILES) {
        const int bx = tile % 3;
        const int rest = tile / 3;
        const int by = rest % 24;
        const int bz = rest / 24;
        const int x0 = bx * TILE_X;
        const int y0 = by * ROWS_PER;
        const uint4* qb = reinterpret_cast<const uint4*>(qin) + (long)bz * Hn * Wn;

        auto slot_of = [&](int gy) { return (gy + 3) % RING; };
        auto async_row = [&](int gy) {
            uint32_t dst0 = smem_u32(&sq[slot_of(gy)][0][0]);
            const bool rowok = (unsigned)gy < (unsigned)Hn;
            const int gyc = rowok ? gy : 0;
            const uint4* rowp = qb + (long)gyc * Wn;
            for (int i = tid; i < 134; i += 128) {
                int gx = x0 - 3 + i;
                bool ok = rowok && (unsigned)gx < (unsigned)Wn;
                int gxc = ((unsigned)gx < (unsigned)Wn) ? gx : 0;
                cpa16(dst0 + (uint32_t)i * 16u, rowp + gxc, ok ? 16 : 0);
            }
        };

        for (int gy = y0 - 3; gy <= y0 + 6; ++gy) async_row(gy);
        cpa_commit();
        cpa_wait0();
        __syncthreads();

        for (int p = 0; p < ROWS_PER / RPASS; ++p) {
            const int y = y0 + p * RPASS;
            if (p < ROWS_PER / RPASS - 1) {
                for (int gy = y + 7; gy <= y + 10; ++gy) async_row(gy);
                cpa_commit();
            }

            float acc[RPASS][8];
#pragma unroll
            for (int r = 0; r < RPASS; ++r)
#pragma unroll
                for (int j = 0; j < 8; ++j) acc[r][j] = 0.f;

            const int slot0 = y % RING;

#pragma unroll
            for (int dxp = 0; dxp < 4; ++dxp) {
                uint2 bf[7];
#pragma unroll
                for (int dy = 0; dy < 7; ++dy) bf[dy] = sbfrag[dy][dxp][lane];

#pragma unroll
                for (int si = 0; si < 10; ++si) {
                    const int sy = si - 3;
                    int slot = slot0 + si;
                    if (slot >= RING) slot -= RING;
                    const uint32_t abase = ring0 + (uint32_t)(slot * (RPITCH * 16))
                                         + wbase + lofs + (uint32_t)(dxp * 32);
                    uint32_t a0, a1, a2, a3, c0, c1, c2, c3;
                    ldm4(a0, a1, a2, a3, abase);
                    ldm4(c0, c1, c2, c3, abase + 256);
                    const int rlo = (sy - 3 < 0) ? 0 : sy - 3;
                    const int rhi = (sy + 3 > RPASS - 1) ? RPASS - 1 : sy + 3;
#pragma unroll
                    for (int r = rlo; r <= rhi; ++r) {
                        const int dy = sy - r + 3;
                        hmma(acc[r], a0, a1, a2, a3, bf[dy].x, bf[dy].y);
                        hmma(acc[r] + 4, c0, c1, c2, c3, bf[dy].x, bf[dy].y);
                    }
                }
            }

            // ---- epilogue: out = -(uW + pen), then softmax / store ----
            const int g = lane >> 2, t = lane & 3;
#pragma unroll
            for (int r = 0; r < RPASS; ++r) {
                __syncwarp();
                *reinterpret_cast<float2*>(&sst[w][g][2 * t])      = make_float2(acc[r][0], acc[r][1]);
                *reinterpret_cast<float2*>(&sst[w][g + 8][2 * t])  = make_float2(acc[r][2], acc[r][3]);
                *reinterpret_cast<float2*>(&sst[w][g + 16][2 * t]) = make_float2(acc[r][4], acc[r][5]);
                *reinterpret_cast<float2*>(&sst[w][g + 24][2 * t]) = make_float2(acc[r][6], acc[r][7]);
                __syncwarp();
                float pen[8];
#pragma unroll
                for (int c = 0; c < 4; ++c) {
                    float2 v = *reinterpret_cast<float2*>(&sst[w][lane][2 * c]);
                    pen[2 * c] = v.x; pen[2 * c + 1] = v.y;
                }

                const long gi = ((long)(bz * Hn + y + r) * Wn + x0 + w * 32 + lane) * 8;
                float4 uA = *reinterpret_cast<const float4*>(uw + gi);
                float4 uB = *reinterpret_cast<const float4*>(uw + gi + 4);
                float out[8];
                out[0] = -(uA.x + pen[0]); out[1] = -(uA.y + pen[1]);
                out[2] = -(uA.z + pen[2]); out[3] = -(uA.w + pen[3]);
                out[4] = -(uB.x + pen[4]); out[5] = -(uB.y + pen[5]);
                out[6] = -(uB.z + pen[6]); out[7] = -(uB.w + pen[7]);

                if (logits_out) {
                    float4* lo = reinterpret_cast<float4*>(logits_out + gi);
                    lo[0] = make_float4(out[0], out[1], out[2], out[3]);
                    lo[1] = make_float4(out[4], out[5], out[6], out[7]);
                } else {
                    float m = out[0];
#pragma unroll
                    for (int c = 1; c < 8; c++) m = fmaxf(m, out[c]);
                    float e[8], s = 0.f;
#pragma unroll
                    for (int c = 0; c < 8; c++) { e[c] = __expf(out[c] - m); s += e[c]; }
                    float inv = 1.f / s;
                    uint4 qv;
                    qv.x = h2pack(e[0] * inv, e[1] * inv);
                    qv.y = h2pack(e[2] * inv, e[3] * inv);
                    qv.z = h2pack(e[4] * inv, e[5] * inv);
                    qv.w = h2pack(e[6] * inv, e[7] * inv);
                    reinterpret_cast<uint4*>(qout)[gi >> 3] = qv;
                }
            }

            if (p < ROWS_PER / RPASS - 1) cpa_wait0();
            __syncthreads();
        }

        // ---- grab next tile ----
        if (tid == 0) s_t = atomicAdd(&g_ctr[ctr_idx], 1);
        __syncthreads();
        tile = s_t;
        __syncthreads();
    }
}

// ============================================================
extern "C" void kernel_launch(void* const* d_in, const int* in_sizes, int n_in,
                              void* d_out, int out_size) {
    const float* x  = (const float*)d_in[0];
    const float* kw = (const float*)d_in[1];
    const float* ws = (const float*)d_in[2];
    const float* bs = (const float*)d_in[3];

    __half *qA, *qB;
    float* uu;
    cudaGetSymbolAddress((void**)&qA, g_qA);
    cudaGetSymbolAddress((void**)&qB, g_qB);
    cudaGetSymbolAddress((void**)&uu, g_u);

    k_init<<<(NPIX + 255) / 256, 256>>>(x, ws, bs, qA, uu);

    __half* src = qA;
    __half* dst = qB;
    for (int it = 0; it < 5; it++) {
        float* lo = (it == 4) ? (float*)d_out : nullptr;
        k_iter<<<GRID_CTAS, 128>>>(src, uu, kw, ws, dst, lo, it);
        __half* t = src; src = dst; dst = t;
    }
}

// round 17
// speedup vs baseline: 1.4736x; 1.0098x over previous
#include <cuda_runtime.h>
#include <cuda_fp16.h>
#include <cstdint>

#define Bn 32
#define Hn 384
#define Wn 384
#define NPIX (Bn*Hn*Wn)          // 4,718,592
#define NELEM (NPIX*8)           // 37,748,736

#define TILE_X 128
#define ROWS_PER 16              // rows per tile
#define RPASS 4                  // output rows per pass
#define RPITCH 136               // smem row pitch in pixels
#define RING 14                  // ring slots = live set (10 + 4 prefetch)

#define GRID_CTAS 740            // 148 SMs x 5 CTAs: one full wave
#define NTILES (3*24*32)         // 2304

// Scratch (__device__ globals: allocation-free rule)
__device__ __half g_qA[NELEM];
__device__ __half g_qB[NELEM];
__device__ float  g_u[NELEM];    // holds uW = W^T u - b (per pixel)
__device__ int    g_ctr[8];      // one tile counter per k_iter launch

// ---------- helpers ----------
__device__ __forceinline__ uint32_t smem_u32(const void* p) {
    uint32_t a;
    asm("{ .reg .u64 t; cvta.to.shared.u64 t, %1; cvt.u32.u64 %0, t; }"
        : "=r"(a) : "l"(p));
    return a;
}
__device__ __forceinline__ void ldm4(uint32_t& a0, uint32_t& a1,
                                     uint32_t& a2, uint32_t& a3, uint32_t addr) {
    asm volatile("ldmatrix.sync.aligned.m8n8.x4.shared.b16 {%0,%1,%2,%3},[%4];"
                 : "=r"(a0), "=r"(a1), "=r"(a2), "=r"(a3) : "r"(addr));
}
__device__ __forceinline__ void hmma(float* d, uint32_t a0, uint32_t a1,
                                     uint32_t a2, uint32_t a3,
                                     uint32_t b0, uint32_t b1) {
    asm volatile("mma.sync.aligned.m16n8k16.row.col.f32.f16.f16.f32 "
                 "{%0,%1,%2,%3},{%4,%5,%6,%7},{%8,%9},{%0,%1,%2,%3};"
                 : "+f"(d[0]), "+f"(d[1]), "+f"(d[2]), "+f"(d[3])
                 : "r"(a0), "r"(a1), "r"(a2), "r"(a3), "r"(b0), "r"(b1));
}
__device__ __forceinline__ void cpa16(uint32_t dst, const void* src, int sz) {
    asm volatile("cp.async.cg.shared.global [%0], [%1], 16, %2;"
                 :: "r"(dst), "l"(src), "r"(sz) : "memory");
}
__device__ __forceinline__ void cpa_commit() {
    asm volatile("cp.async.commit_group;" ::: "memory");
}
__device__ __forceinline__ void cpa_wait0() {
    asm volatile("cp.async.wait_group 0;" ::: "memory");
}
__device__ __forceinline__ uint32_t h2pack(float a, float b) {
    __half2 h = __floats2half2_rn(a, b);
    return *reinterpret_cast<uint32_t*>(&h);
}

// ============================================================
// init: q0 = softmax(x) (fp16);
//       uW = W^T * (-log(max(q0,1e-6))) - b   (fp32, per pixel)
// Also resets the per-launch tile counters.
// ============================================================
__global__ void k_init(const float* __restrict__ x,
                       const float* __restrict__ wsc,   // [8,8] W[c][d]
                       const float* __restrict__ bsc,   // [8]
                       __half* __restrict__ q,
                       float* __restrict__ uw) {
    __shared__ float sW[64];
    __shared__ float sB[8];
    int gti = blockIdx.x * blockDim.x + threadIdx.x;
    if (threadIdx.x < 64) sW[threadIdx.x] = wsc[threadIdx.x];
    if (threadIdx.x < 8)  sB[threadIdx.x] = bsc[threadIdx.x];
    if (gti < 8) g_ctr[gti] = GRID_CTAS;
    __syncthreads();
    int i = gti;
    if (i >= NPIX) return;
    const float4* xp = reinterpret_cast<const float4*>(x) + (long)i * 2;
    float4 a = xp[0], b4 = xp[1];
    float v[8] = {a.x, a.y, a.z, a.w, b4.x, b4.y, b4.z, b4.w};
    float m = v[0];
#pragma unroll
    for (int c = 1; c < 8; c++) m = fmaxf(m, v[c]);
    float e[8], s = 0.f;
#pragma unroll
    for (int c = 0; c < 8; c++) { e[c] = __expf(v[c] - m); s += e[c]; }
    float inv = 1.f / s;
    float qq[8], uu[8];
#pragma unroll
    for (int c = 0; c < 8; c++) {
        qq[c] = e[c] * inv;
        uu[c] = -__logf(fmaxf(qq[c], 1e-6f));
    }

    uint4 qv;
    qv.x = h2pack(qq[0], qq[1]);
    qv.y = h2pack(qq[2], qq[3]);
    qv.z = h2pack(qq[4], qq[5]);
    qv.w = h2pack(qq[6], qq[7]);
    reinterpret_cast<uint4*>(q)[i] = qv;

    float uwv[8];
#pragma unroll
    for (int d = 0; d < 8; d++) {
        float acc = -sB[d];
#pragma unroll
        for (int c = 0; c < 8; c++) acc = fmaf(uu[c], sW[c * 8 + d], acc);
        uwv[d] = acc;
    }
    float4* up = reinterpret_cast<float4*>(uw) + (long)i * 2;
    up[0] = make_float4(uwv[0], uwv[1], uwv[2], uwv[3]);
    up[1] = make_float4(uwv[4], uwv[5], uwv[6], uwv[7]);
}

// ============================================================
// One mean-field iteration. Persistent CTAs pull tiles from an
// atomic queue (next-tile grab issued early, latency hidden).
// k' = k.W folded into B fragments; out = -(uW + conv(q,k')).
// uw loads for all 4 epilogue rows batched (MLP=8).
// ============================================================
__global__ __launch_bounds__(128, 5)
void k_iter(const __half* __restrict__ qin,
            const float* __restrict__ uw,
            const float* __restrict__ kw,      // [7,7,8,8] fp32
            const float* __restrict__ wsc,     // [8,8] (for k' fold)
            __half* __restrict__ qout,
            float* __restrict__ logits_out,    // non-null on last iter
            int ctr_idx) {
    __shared__ __align__(16) __half sq[RING][RPITCH][8];  // 30,464 B
    __shared__ __align__(16) uint2  sbfrag[7][4][32];     // 7,168 B
    __shared__ __align__(16) float  sst[4][32][10];       // 5,120 B
    __shared__ float sW[64];
    __shared__ int   s_t;

    const int tid = threadIdx.x;
    const int w = tid >> 5;
    const int lane = tid & 31;

    if (tid < 64) sW[tid] = wsc[tid];
    __syncthreads();

    // ---- B fragments (once per CTA): k'[dy][dx][ci][d] = sum_co kmask*W ----
    for (int idx = tid; idx < 7 * 4 * 32; idx += 128) {
        int l = idx & 31, dxp = (idx >> 5) & 3, dy = idx >> 7;
        int t = l & 3, g = l >> 2;
        int dx0 = dxp * 2, dx1 = dx0 + 1;
        int c0 = 2 * t, c1 = 2 * t + 1;
        float w00 = 0.f, w01 = 0.f, w10 = 0.f, w11 = 0.f;
#pragma unroll
        for (int co = 0; co < 8; co++) {
            float wg = sW[co * 8 + g];
            if (co != c0) w00 = fmaf(__ldg(&kw[((dy * 7 + dx0) * 8 + c0) * 8 + co]), wg, w00);
            if (co != c1) w01 = fmaf(__ldg(&kw[((dy * 7 + dx0) * 8 + c1) * 8 + co]), wg, w01);
            if (dx1 < 7) {
                if (co != c0) w10 = fmaf(__ldg(&kw[((dy * 7 + dx1) * 8 + c0) * 8 + co]), wg, w10);
                if (co != c1) w11 = fmaf(__ldg(&kw[((dy * 7 + dx1) * 8 + c1) * 8 + co]), wg, w11);
            }
        }
        sbfrag[dy][dxp][l] = make_uint2(h2pack(w00, w01), h2pack(w10, w11));
    }
    if (tid < 2 * RING) {  // zero slack pixels 134,135 of every ring slot
        uint4 z = make_uint4(0, 0, 0, 0);
        *reinterpret_cast<uint4*>(&sq[tid >> 1][134 + (tid & 1)][0]) = z;
    }

    const uint32_t ring0 = smem_u32(sq);
    const uint32_t lofs = (uint32_t)(((lane & 15) + (lane >> 4)) * 16);
    const uint32_t wbase = (uint32_t)(w * 32 * 16);

    int tile = blockIdx.x;          // first tile without touching the counter

    while (tile < NTILES) {
        const int bx = tile % 3;
        const int rest = tile / 3;
        const int by = rest % 24;
        const int bz = rest / 24;
        const int x0 = bx * TILE_X;
        const int y0 = by * ROWS_PER;
        const uint4* qb = reinterpret_cast<const uint4*>(qin) + (long)bz * Hn * Wn;

        auto slot_of = [&](int gy) { return (gy + 3) % RING; };
        auto async_row = [&](int gy) {
            uint32_t dst0 = smem_u32(&sq[slot_of(gy)][0][0]);
            const bool rowok = (unsigned)gy < (unsigned)Hn;
            const int gyc = rowok ? gy : 0;
            const uint4* rowp = qb + (long)gyc * Wn;
            for (int i = tid; i < 134; i += 128) {
                int gx = x0 - 3 + i;
                bool ok = rowok && (unsigned)gx < (unsigned)Wn;
                int gxc = ((unsigned)gx < (unsigned)Wn) ? gx : 0;
                cpa16(dst0 + (uint32_t)i * 16u, rowp + gxc, ok ? 16 : 0);
            }
        };

        for (int gy = y0 - 3; gy <= y0 + 6; ++gy) async_row(gy);
        cpa_commit();
        cpa_wait0();
        __syncthreads();

        // early grab of the NEXT tile: ATOMG latency hidden behind this
        // tile's work. s_t not read by anyone until after the final pass's
        // __syncthreads; previous read happened before the barrier above.
        if (tid == 0) s_t = atomicAdd(&g_ctr[ctr_idx], 1);

        for (int p = 0; p < ROWS_PER / RPASS; ++p) {
            const int y = y0 + p * RPASS;
            if (p < ROWS_PER / RPASS - 1) {
                for (int gy = y + 7; gy <= y + 10; ++gy) async_row(gy);
                cpa_commit();
            }

            float acc[RPASS][8];
#pragma unroll
            for (int r = 0; r < RPASS; ++r)
#pragma unroll
                for (int j = 0; j < 8; ++j) acc[r][j] = 0.f;

            const int slot0 = y % RING;

#pragma unroll
            for (int dxp = 0; dxp < 4; ++dxp) {
                uint2 bf[7];
#pragma unroll
                for (int dy = 0; dy < 7; ++dy) bf[dy] = sbfrag[dy][dxp][lane];

#pragma unroll
                for (int si = 0; si < 10; ++si) {
                    const int sy = si - 3;
                    int slot = slot0 + si;
                    if (slot >= RING) slot -= RING;
                    const uint32_t abase = ring0 + (uint32_t)(slot * (RPITCH * 16))
                                         + wbase + lofs + (uint32_t)(dxp * 32);
                    uint32_t a0, a1, a2, a3, c0, c1, c2, c3;
                    ldm4(a0, a1, a2, a3, abase);
                    ldm4(c0, c1, c2, c3, abase + 256);
                    const int rlo = (sy - 3 < 0) ? 0 : sy - 3;
                    const int rhi = (sy + 3 > RPASS - 1) ? RPASS - 1 : sy + 3;
#pragma unroll
                    for (int r = rlo; r <= rhi; ++r) {
                        const int dy = sy - r + 3;
                        hmma(acc[r], a0, a1, a2, a3, bf[dy].x, bf[dy].y);
                        hmma(acc[r] + 4, c0, c1, c2, c3, bf[dy].x, bf[dy].y);
                    }
                }
            }

            // ---- batched uw loads: 8 independent LDG.128 (MLP=8) ----
            const long gi0 = ((long)(bz * Hn + y) * Wn + x0 + w * 32 + lane) * 8;
            float4 uA[RPASS], uB[RPASS];
#pragma unroll
            for (int r = 0; r < RPASS; ++r) {
                const long gir = gi0 + (long)r * Wn * 8;
                uA[r] = *reinterpret_cast<const float4*>(uw + gir);
                uB[r] = *reinterpret_cast<const float4*>(uw + gir + 4);
            }

            // ---- epilogue: out = -(uW + pen), then softmax / store ----
            const int g = lane >> 2, t = lane & 3;
#pragma unroll
            for (int r = 0; r < RPASS; ++r) {
                __syncwarp();
                *reinterpret_cast<float2*>(&sst[w][g][2 * t])      = make_float2(acc[r][0], acc[r][1]);
                *reinterpret_cast<float2*>(&sst[w][g + 8][2 * t])  = make_float2(acc[r][2], acc[r][3]);
                *reinterpret_cast<float2*>(&sst[w][g + 16][2 * t]) = make_float2(acc[r][4], acc[r][5]);
                *reinterpret_cast<float2*>(&sst[w][g + 24][2 * t]) = make_float2(acc[r][6], acc[r][7]);
                __syncwarp();
                float pen[8];
#pragma unroll
                for (int c = 0; c < 4; ++c) {
                    float2 v = *reinterpret_cast<float2*>(&sst[w][lane][2 * c]);
                    pen[2 * c] = v.x; pen[2 * c + 1] = v.y;
                }

                const long gi = gi0 + (long)r * Wn * 8;
                float out[8];
                out[0] = -(uA[r].x + pen[0]); out[1] = -(uA[r].y + pen[1]);
                out[2] = -(uA[r].z + pen[2]); out[3] = -(uA[r].w + pen[3]);
                out[4] = -(uB[r].x + pen[4]); out[5] = -(uB[r].y + pen[5]);
                out[6] = -(uB[r].z + pen[6]); out[7] = -(uB[r].w + pen[7]);

                if (logits_out) {
                    float4* lo = reinterpret_cast<float4*>(logits_out + gi);
                    lo[0] = make_float4(out[0], out[1], out[2], out[3]);
                    lo[1] = make_float4(out[4], out[5], out[6], out[7]);
                } else {
                    float m = out[0];
#pragma unroll
                    for (int c = 1; c < 8; c++) m = fmaxf(m, out[c]);
                    float e[8], s = 0.f;
#pragma unroll
                    for (int c = 0; c < 8; c++) { e[c] = __expf(out[c] - m); s += e[c]; }
                    float inv = 1.f / s;
                    uint4 qv;
                    qv.x = h2pack(e[0] * inv, e[1] * inv);
                    qv.y = h2pack(e[2] * inv, e[3] * inv);
                    qv.z = h2pack(e[4] * inv, e[5] * inv);
                    qv.w = h2pack(e[6] * inv, e[7] * inv);
                    reinterpret_cast<uint4*>(qout)[gi >> 3] = qv;
                }
            }

            if (p < ROWS_PER / RPASS - 1) cpa_wait0();
            __syncthreads();
        }

        // final pass ended with __syncthreads(): s_t (written early) is
        // visible to all threads, and everyone is past the ring reads.
        tile = s_t;
    }
}

// ============================================================
extern "C" void kernel_launch(void* const* d_in, const int* in_sizes, int n_in,
                              void* d_out, int out_size) {
    const float* x  = (const float*)d_in[0];
    const float* kw = (const float*)d_in[1];
    const float* ws = (const float*)d_in[2];
    const float* bs = (const float*)d_in[3];

    __half *qA, *qB;
    float* uu;
    cudaGetSymbolAddress((void**)&qA, g_qA);
    cudaGetSymbolAddress((void**)&qB, g_qB);
    cudaGetSymbolAddress((void**)&uu, g_u);

    k_init<<<(NPIX + 255) / 256, 256>>>(x, ws, bs, qA, uu);

    __half* src = qA;
    __half* dst = qB;
    for (int it = 0; it < 5; it++) {
        float* lo = (it == 4) ? (float*)d_out : nullptr;
        k_iter<<<GRID_CTAS, 128>>>(src, uu, kw, ws, dst, lo, it);
        __half* t = src; src = dst; dst = t;
    }
}